// round 7
// baseline (speedup 1.0000x reference)
#include <cuda_runtime.h>
#include <cuda_fp16.h>
#include <cstdint>

#define BATCH 4
#define SEQ   2048
#define DMODEL 1024
#define NHEAD 16
#define DHEAD 64
#define NTOK  (BATCH*SEQ)   // 8192
#define MM    (DMODEL*DMODEL)

// ---------------- scratch (__device__ globals: allocation-free) ----------------
__device__ __align__(16) __half g_Ahi[NTOK*DMODEL];
__device__ __align__(16) __half g_Alo[NTOK*DMODEL];
__device__ __align__(16) __half g_WhT[4*MM];          // [N,K] transposed fp16 hi only
__device__ __align__(16) __half g_Qhi[NTOK*DMODEL];
__device__ __align__(16) __half g_Qlo[NTOK*DMODEL];
__device__ __align__(16) __half g_Khi[NTOK*DMODEL];
__device__ __align__(16) __half g_Vhi[NTOK*DMODEL];
__device__ __align__(16) __half g_VThi[NTOK*DMODEL]; // [b,h,dh,seq]
__device__ __align__(16) __half g_Zhi[NTOK*DMODEL];
__device__ __align__(16) __half g_Zlo[NTOK*DMODEL];

__device__ __forceinline__ uint32_t smem_u32(const void* p) {
    uint32_t a;
    asm("{ .reg .u64 t; cvta.to.shared.u64 t, %1; cvt.u32.u64 %0, t; }" : "=r"(a) : "l"(p));
    return a;
}

#define MMA_F16(acc, a, b) \
    asm volatile("mma.sync.aligned.m16n8k16.row.col.f32.f16.f16.f32 " \
        "{%0,%1,%2,%3}, {%4,%5,%6,%7}, {%8,%9}, {%0,%1,%2,%3};" \
        : "+f"((acc)[0]), "+f"((acc)[1]), "+f"((acc)[2]), "+f"((acc)[3]) \
        : "r"((a)[0]), "r"((a)[1]), "r"((a)[2]), "r"((a)[3]), "r"((b)[0]), "r"((b)[1]))

#define CPA16(dst, src) \
    asm volatile("cp.async.cg.shared.global [%0], [%1], 16;" :: "r"(dst), "l"(src) : "memory")

// ---------------- conversion kernels (fp32 -> fp16 hi/lo split) ----------------
__device__ __forceinline__ void split2h(float a, float b, __half2& h, __half2& l) {
    __half ha = __float2half_rn(a), hb = __float2half_rn(b);
    __half la = __float2half_rn(a - __half2float(ha));
    __half lb = __float2half_rn(b - __half2float(hb));
    h = __halves2half2(ha, hb);
    l = __halves2half2(la, lb);
}

__global__ void __launch_bounds__(256) conv_resid(const float* __restrict__ src) {
    int i = blockIdx.x * 256 + threadIdx.x;
    float4 v = ((const float4*)src)[i];
    __half2 h01, l01, h23, l23;
    split2h(v.x, v.y, h01, l01);
    split2h(v.z, v.w, h23, l23);
    ((__half2*)g_Ahi)[2*i]   = h01; ((__half2*)g_Ahi)[2*i+1] = h23;
    ((__half2*)g_Alo)[2*i]   = l01; ((__half2*)g_Alo)[2*i+1] = l23;
}

// All 4 weights in one launch: blockIdx.z = widx; widx==3 applies [dh,h,d] row remap.
__global__ void __launch_bounds__(1024) conv_W4(const float* __restrict__ WQ,
                                                const float* __restrict__ WK,
                                                const float* __restrict__ WV,
                                                const float* __restrict__ WO) {
    __shared__ float t[32][33];
    int widx = blockIdx.z;
    const float* src = (widx == 0) ? WQ : (widx == 1) ? WK : (widx == 2) ? WV : WO;
    int tx = threadIdx.x, ty = threadIdx.y;
    int k = blockIdx.y * 32 + ty, n = blockIdx.x * 32 + tx;
    int sk = (widx == 3) ? ((k & 63) * 16 + (k >> 6)) : k;
    t[ty][tx] = src[sk * DMODEL + n];
    __syncthreads();
    int n2 = blockIdx.x * 32 + ty, k2 = blockIdx.y * 32 + tx;
    g_WhT[(size_t)widx * MM + (size_t)n2 * DMODEL + k2] = __float2half_rn(t[tx][ty]);
}

// V [token][h*64+dh] -> VT [b,h,dh,seq]
__global__ void __launch_bounds__(256) trans_V() {
    __shared__ __half t[32][33];
    int tx = threadIdx.x, ty = threadIdx.y;   // 32 x 8
    int bh = blockIdx.y >> 1, dt = blockIdx.y & 1;
    int b = bh >> 4, h = bh & 15;
    #pragma unroll
    for (int j = 0; j < 4; j++) {
        int s = blockIdx.x * 32 + ty + j * 8;
        t[ty + j*8][tx] = g_Vhi[(size_t)(b*SEQ + s) * DMODEL + h*64 + dt*32 + tx];
    }
    __syncthreads();
    #pragma unroll
    for (int j = 0; j < 4; j++) {
        int dh = dt*32 + ty + j*8;
        g_VThi[(size_t)(bh*64 + dh) * SEQ + blockIdx.x*32 + tx] = t[tx][ty + j*8];
    }
}

// ---------------- 2-pass split-fp16 HMMA GEMM: C = alpha*((Ahi+Alo)@Bh^T) ----------------
#define KC    32
#define NCH   (DMODEL / KC)
#define NSTG  3
#define APAD  40
#define ROWB  (APAD * 2)
#define TILE_B (128 * ROWB)
#define STG_B  (3 * TILE_B)     // Ahi, Alo, Bh
#define GEMM_SMEM (NSTG * STG_B)   // 92160

__device__ __forceinline__ void load_tile(uint32_t sdst, const __half* __restrict__ g,
                                          int row0, int k0, int tid) {
    const char* gb = (const char*)(g + (size_t)row0 * DMODEL + k0);
    #pragma unroll
    for (int i = 0; i < 2; i++) {
        int id = i * 256 + tid;
        int r = id >> 2, c = id & 3;
        uint32_t sd = sdst + (uint32_t)(r * ROWB + c * 16);
        const char* gp = gb + (size_t)r * (DMODEL * 2) + c * 16;
        CPA16(sd, gp);
    }
}

// OUTMODE 0: fp32 C + bias; 1: hi+lo fp16 outputs; 2: hi-only fp16 output
template<int OUTMODE>
__device__ __forceinline__ void gemm_hmma(const __half* __restrict__ Ahi,
                                          const __half* __restrict__ Alo,
                                          const __half* __restrict__ Bh,
                                          float* __restrict__ C,
                                          const float* __restrict__ bias,
                                          __half* __restrict__ Chi,
                                          __half* __restrict__ Clo,
                                          float alpha)
{
    extern __shared__ char sm[];
    uint32_t sbase = smem_u32(sm);

    int tid  = threadIdx.x;
    int wid  = tid >> 5, lane = tid & 31;
    int gr   = lane >> 2;
    int lc2  = (lane & 3) * 2;
    int wm   = (wid & 3) * 32;
    int wn   = (wid >> 2) * 64;
    int brow = blockIdx.y * 128;
    int bcol = blockIdx.x * 128;

    float acc[2][8][4];
    #pragma unroll
    for (int i = 0; i < 2; i++)
        #pragma unroll
        for (int j = 0; j < 8; j++)
            #pragma unroll
            for (int q = 0; q < 4; q++) acc[i][j][q] = 0.f;

    #pragma unroll
    for (int s = 0; s < NSTG; s++) {
        uint32_t stg = sbase + s * STG_B;
        int k0 = s * KC;
        load_tile(stg,            Ahi, brow, k0, tid);
        load_tile(stg + TILE_B,   Alo, brow, k0, tid);
        load_tile(stg + 2*TILE_B, Bh,  bcol, k0, tid);
        asm volatile("cp.async.commit_group;" ::: "memory");
    }

    for (int c = 0; c < NCH; c++) {
        int rem = NCH - 1 - c;
        if (rem >= 2)      asm volatile("cp.async.wait_group 2;" ::: "memory");
        else if (rem == 1) asm volatile("cp.async.wait_group 1;" ::: "memory");
        else               asm volatile("cp.async.wait_group 0;" ::: "memory");
        __syncthreads();

        const char* stg = sm + (size_t)(c % NSTG) * STG_B;
        const char* pAh = stg;
        const char* pAl = stg + TILE_B;
        const char* pBh = stg + 2*TILE_B;

        #pragma unroll
        for (int ks = 0; ks < 2; ks++) {
            int k0b = ks * 32;
            uint32_t ah[2][4], al[2][4], bh[8][2];
            #pragma unroll
            for (int mt = 0; mt < 2; mt++) {
                const char* p = pAh + (wm + mt*16 + gr) * ROWB + k0b + lc2*2;
                ah[mt][0] = *(const uint32_t*)p;
                ah[mt][1] = *(const uint32_t*)(p + 8*ROWB);
                ah[mt][2] = *(const uint32_t*)(p + 16);
                ah[mt][3] = *(const uint32_t*)(p + 8*ROWB + 16);
                const char* q = pAl + (wm + mt*16 + gr) * ROWB + k0b + lc2*2;
                al[mt][0] = *(const uint32_t*)q;
                al[mt][1] = *(const uint32_t*)(q + 8*ROWB);
                al[mt][2] = *(const uint32_t*)(q + 16);
                al[mt][3] = *(const uint32_t*)(q + 8*ROWB + 16);
            }
            #pragma unroll
            for (int nt = 0; nt < 8; nt++) {
                const char* p = pBh + (wn + nt*8 + gr) * ROWB + k0b + lc2*2;
                bh[nt][0] = *(const uint32_t*)p;
                bh[nt][1] = *(const uint32_t*)(p + 16);
            }
            #pragma unroll
            for (int mt = 0; mt < 2; mt++)
                #pragma unroll
                for (int nt = 0; nt < 8; nt++) {
                    MMA_F16(acc[mt][nt], ah[mt], bh[nt]);
                    MMA_F16(acc[mt][nt], al[mt], bh[nt]);
                }
        }
        __syncthreads();

        if (c + NSTG < NCH) {
            uint32_t stg2 = sbase + ((c + NSTG) % NSTG) * STG_B;
            int k0 = (c + NSTG) * KC;
            load_tile(stg2,            Ahi, brow, k0, tid);
            load_tile(stg2 + TILE_B,   Alo, brow, k0, tid);
            load_tile(stg2 + 2*TILE_B, Bh,  bcol, k0, tid);
            asm volatile("cp.async.commit_group;" ::: "memory");
        }
    }

    #pragma unroll
    for (int mt = 0; mt < 2; mt++) {
        int r0 = brow + wm + mt*16 + gr;
        #pragma unroll
        for (int nt = 0; nt < 8; nt++) {
            int c0 = bcol + wn + nt*8 + lc2;
            if (OUTMODE == 0) {
                float bx = bias[c0], by = bias[c0 + 1];
                float2 v0, v1;
                v0.x = acc[mt][nt][0] * alpha + bx;
                v0.y = acc[mt][nt][1] * alpha + by;
                v1.x = acc[mt][nt][2] * alpha + bx;
                v1.y = acc[mt][nt][3] * alpha + by;
                *(float2*)&C[(size_t)r0 * DMODEL + c0]       = v0;
                *(float2*)&C[(size_t)(r0 + 8) * DMODEL + c0] = v1;
            } else if (OUTMODE == 1) {
                __half2 h, l;
                split2h(acc[mt][nt][0] * alpha, acc[mt][nt][1] * alpha, h, l);
                *(__half2*)&Chi[(size_t)r0 * DMODEL + c0] = h;
                *(__half2*)&Clo[(size_t)r0 * DMODEL + c0] = l;
                split2h(acc[mt][nt][2] * alpha, acc[mt][nt][3] * alpha, h, l);
                *(__half2*)&Chi[(size_t)(r0+8) * DMODEL + c0] = h;
                *(__half2*)&Clo[(size_t)(r0+8) * DMODEL + c0] = l;
            } else {
                *(__half2*)&Chi[(size_t)r0 * DMODEL + c0] =
                    __floats2half2_rn(acc[mt][nt][0] * alpha, acc[mt][nt][1] * alpha);
                *(__half2*)&Chi[(size_t)(r0+8) * DMODEL + c0] =
                    __floats2half2_rn(acc[mt][nt][2] * alpha, acc[mt][nt][3] * alpha);
            }
        }
    }
}

__global__ void __launch_bounds__(256, 2) qkv_tc_kernel() {
    int z = blockIdx.z;
    const __half* Bh = g_WhT + (size_t)z * MM;
    if (z == 0)
        gemm_hmma<1>(g_Ahi, g_Alo, Bh, nullptr, nullptr, g_Qhi, g_Qlo, 0.125f);
    else if (z == 1)
        gemm_hmma<2>(g_Ahi, g_Alo, Bh, nullptr, nullptr, g_Khi, nullptr, 1.0f);
    else
        gemm_hmma<2>(g_Ahi, g_Alo, Bh, nullptr, nullptr, g_Vhi, nullptr, 1.0f);
}

__global__ void __launch_bounds__(256, 2) out_tc_kernel(const float* __restrict__ bias,
                                                        float* __restrict__ out) {
    gemm_hmma<0>(g_Zhi, g_Zlo, g_WhT + 3ull*MM, out, bias, nullptr, nullptr, 1.0f);
}

// ---------------- 2-pass split-fp16 flash attention (causal) ----------------
#define AROW 144
#define QREG (128 * AROW)
#define TREG (64 * AROW)
#define STAGE2 (2 * TREG)        // Khi, VThi
#define ATT2_SMEM (2*QREG + 2*STAGE2)   // 73728

__device__ __forceinline__ void load_att_stage(uint32_t dst, int b, int h, int kt, int tid) {
    int s0 = kt * 64;
    const char* gkh = (const char*)g_Khi  + ((size_t)(b*SEQ + s0) * DMODEL + h*64) * 2;
    const char* gvh = (const char*)g_VThi + ((size_t)((b*NHEAD + h) * DHEAD) * SEQ + s0) * 2;
    #pragma unroll
    for (int i = 0; i < 2; i++) {
        int idx = i * 256 + tid;
        int r = idx >> 3, c = idx & 7;
        uint32_t off = (uint32_t)(r * AROW + c * 16);
        CPA16(dst + off,        gkh + (size_t)r * (DMODEL*2) + c*16);
        CPA16(dst + TREG + off, gvh + (size_t)r * (SEQ*2) + c*16);
    }
}

__global__ void __launch_bounds__(256, 1) attn2_kernel() {
    extern __shared__ char sm[];
    uint32_t sq = smem_u32(sm);

    int tid = threadIdx.x, wid = tid >> 5, lane = tid & 31;
    int gr = lane >> 2, lq = (lane & 3) * 2;
    int qt = blockIdx.x, h = blockIdx.y, b = blockIdx.z;
    int q0 = qt * 128, wm = wid * 16;

    {
        const char* gqh = (const char*)g_Qhi + ((size_t)(b*SEQ + q0) * DMODEL + h*64) * 2;
        const char* gql = (const char*)g_Qlo + ((size_t)(b*SEQ + q0) * DMODEL + h*64) * 2;
        #pragma unroll
        for (int i = 0; i < 4; i++) {
            int idx = i * 256 + tid;
            int r = idx >> 3, c = idx & 7;
            uint32_t off = (uint32_t)(r * AROW + c * 16);
            CPA16(sq + off,        gqh + (size_t)r * (DMODEL*2) + c*16);
            CPA16(sq + QREG + off, gql + (size_t)r * (DMODEL*2) + c*16);
        }
    }
    load_att_stage(sq + 2*QREG, b, h, 0, tid);
    asm volatile("cp.async.commit_group;" ::: "memory");

    int nkt = 2*qt + 2;
    float m0 = -1e30f, m1 = -1e30f, l0 = 0.f, l1 = 0.f;
    float O[8][4];
    #pragma unroll
    for (int i = 0; i < 8; i++)
        #pragma unroll
        for (int j = 0; j < 4; j++) O[i][j] = 0.f;

    const char* qhi = sm;
    int r0g = q0 + wm + gr, r1g = r0g + 8;

    for (int kt = 0; kt < nkt; kt++) {
        int buf = kt & 1;
        if (kt + 1 < nkt) {
            load_att_stage(sq + 2*QREG + (buf^1)*STAGE2, b, h, kt + 1, tid);
            asm volatile("cp.async.commit_group;" ::: "memory");
            asm volatile("cp.async.wait_group 1;" ::: "memory");
        } else {
            asm volatile("cp.async.wait_group 0;" ::: "memory");
        }
        __syncthreads();

        int s0 = kt * 64;
        if (s0 <= q0 + wm + 15) {
            const char* st  = sm + 2*QREG + buf*STAGE2;
            const char* kh  = st;
            const char* vth = st + TREG;

            float S[8][4];
            #pragma unroll
            for (int i = 0; i < 8; i++)
                #pragma unroll
                for (int j = 0; j < 4; j++) S[i][j] = 0.f;

            #pragma unroll
            for (int ks = 0; ks < 4; ks++) {
                const char* pa = qhi + (wm + gr) * AROW + ks*32 + lq*2;
                uint32_t ah[4], al[4];
                ah[0] = *(const uint32_t*)pa;
                ah[1] = *(const uint32_t*)(pa + 8*AROW);
                ah[2] = *(const uint32_t*)(pa + 16);
                ah[3] = *(const uint32_t*)(pa + 8*AROW + 16);
                al[0] = *(const uint32_t*)(pa + QREG);
                al[1] = *(const uint32_t*)(pa + QREG + 8*AROW);
                al[2] = *(const uint32_t*)(pa + QREG + 16);
                al[3] = *(const uint32_t*)(pa + QREG + 8*AROW + 16);
                #pragma unroll
                for (int nt = 0; nt < 8; nt++) {
                    const char* pb = kh + (nt*8 + gr) * AROW + ks*32 + lq*2;
                    uint32_t bh[2];
                    bh[0] = *(const uint32_t*)pb;
                    bh[1] = *(const uint32_t*)(pb + 16);
                    MMA_F16(S[nt], ah, bh);
                    MMA_F16(S[nt], al, bh);
                }
            }

            if (s0 + 63 > q0 + wm) {
                #pragma unroll
                for (int nt = 0; nt < 8; nt++) {
                    int c0 = s0 + nt*8 + lq;
                    if (c0     > r0g) S[nt][0] = -1e30f;
                    if (c0 + 1 > r0g) S[nt][1] = -1e30f;
                    if (c0     > r1g) S[nt][2] = -1e30f;
                    if (c0 + 1 > r1g) S[nt][3] = -1e30f;
                }
            }

            float mx0 = -1e30f, mx1 = -1e30f;
            #pragma unroll
            for (int nt = 0; nt < 8; nt++) {
                mx0 = fmaxf(mx0, fmaxf(S[nt][0], S[nt][1]));
                mx1 = fmaxf(mx1, fmaxf(S[nt][2], S[nt][3]));
            }
            mx0 = fmaxf(mx0, __shfl_xor_sync(0xffffffffu, mx0, 1));
            mx0 = fmaxf(mx0, __shfl_xor_sync(0xffffffffu, mx0, 2));
            mx1 = fmaxf(mx1, __shfl_xor_sync(0xffffffffu, mx1, 1));
            mx1 = fmaxf(mx1, __shfl_xor_sync(0xffffffffu, mx1, 2));
            float mn0 = fmaxf(m0, mx0), mn1 = fmaxf(m1, mx1);
            float a0 = __expf(m0 - mn0), a1 = __expf(m1 - mn1);

            float sum0 = 0.f, sum1 = 0.f;
            uint32_t pH[8][2], pL[8][2];
            #pragma unroll
            for (int nt = 0; nt < 8; nt++) {
                float p0 = __expf(S[nt][0] - mn0);
                float p1 = __expf(S[nt][1] - mn0);
                float p2 = __expf(S[nt][2] - mn1);
                float p3 = __expf(S[nt][3] - mn1);
                sum0 += p0 + p1; sum1 += p2 + p3;
                __half2 hh, ll;
                split2h(p0, p1, hh, ll);
                pH[nt][0] = *(uint32_t*)&hh; pL[nt][0] = *(uint32_t*)&ll;
                split2h(p2, p3, hh, ll);
                pH[nt][1] = *(uint32_t*)&hh; pL[nt][1] = *(uint32_t*)&ll;
            }
            sum0 += __shfl_xor_sync(0xffffffffu, sum0, 1);
            sum0 += __shfl_xor_sync(0xffffffffu, sum0, 2);
            sum1 += __shfl_xor_sync(0xffffffffu, sum1, 1);
            sum1 += __shfl_xor_sync(0xffffffffu, sum1, 2);

            m0 = mn0; m1 = mn1;
            l0 = l0 * a0 + sum0;
            l1 = l1 * a1 + sum1;
            #pragma unroll
            for (int nt = 0; nt < 8; nt++) {
                O[nt][0] *= a0; O[nt][1] *= a0;
                O[nt][2] *= a1; O[nt][3] *= a1;
            }

            #pragma unroll
            for (int ks = 0; ks < 4; ks++) {
                uint32_t aH[4] = { pH[2*ks][0], pH[2*ks][1], pH[2*ks+1][0], pH[2*ks+1][1] };
                uint32_t aL[4] = { pL[2*ks][0], pL[2*ks][1], pL[2*ks+1][0], pL[2*ks+1][1] };
                #pragma unroll
                for (int nt = 0; nt < 8; nt++) {
                    const char* pv = vth + (nt*8 + gr) * AROW + ks*32 + lq*2;
                    uint32_t bvh[2];
                    bvh[0] = *(const uint32_t*)pv;
                    bvh[1] = *(const uint32_t*)(pv + 16);
                    MMA_F16(O[nt], aH, bvh);
                    MMA_F16(O[nt], aL, bvh);
                }
            }
        }
        __syncthreads();
    }

    float inv0 = 1.f / l0, inv1 = 1.f / l1;
    size_t t0 = (size_t)(b*SEQ + q0 + wm + gr) * DMODEL + h*64;
    size_t t1 = t0 + 8 * DMODEL;
    #pragma unroll
    for (int nt = 0; nt < 8; nt++) {
        int c0 = nt*8 + lq;
        __half2 hh, ll;
        split2h(O[nt][0] * inv0, O[nt][1] * inv0, hh, ll);
        *(__half2*)&g_Zhi[t0 + c0] = hh;
        *(__half2*)&g_Zlo[t0 + c0] = ll;
        split2h(O[nt][2] * inv1, O[nt][3] * inv1, hh, ll);
        *(__half2*)&g_Zhi[t1 + c0] = hh;
        *(__half2*)&g_Zlo[t1 + c0] = ll;
    }
}

// ---------------------------------------------------------------------------
extern "C" void kernel_launch(void* const* d_in, const int* in_sizes, int n_in,
                              void* d_out, int out_size)
{
    const float* resid = (const float*)d_in[0];
    const float* WQ    = (const float*)d_in[1];
    const float* WK    = (const float*)d_in[2];
    const float* WV    = (const float*)d_in[3];
    const float* Wout  = (const float*)d_in[4];
    const float* bout  = (const float*)d_in[5];
    float* out = (float*)d_out;

    cudaFuncSetAttribute(qkv_tc_kernel, cudaFuncAttributeMaxDynamicSharedMemorySize, GEMM_SMEM);
    cudaFuncSetAttribute(out_tc_kernel, cudaFuncAttributeMaxDynamicSharedMemorySize, GEMM_SMEM);
    cudaFuncSetAttribute(attn2_kernel,  cudaFuncAttributeMaxDynamicSharedMemorySize, ATT2_SMEM);

    conv_resid<<<NTOK*DMODEL/4/256, 256>>>(resid);
    conv_W4<<<dim3(32, 32, 4), dim3(32, 32)>>>(WQ, WK, WV, Wout);

    qkv_tc_kernel<<<dim3(DMODEL/128, NTOK/128, 3), 256, GEMM_SMEM>>>();

    trans_V<<<dim3(SEQ/32, 2*BATCH*NHEAD), dim3(32, 8)>>>();

    attn2_kernel<<<dim3(SEQ/128, NHEAD, BATCH), 256, ATT2_SMEM>>>();

    out_tc_kernel<<<dim3(DMODEL/128, NTOK/128, 1), 256, GEMM_SMEM>>>(bout, out);
}

// round 8
// speedup vs baseline: 1.1309x; 1.1309x over previous
#include <cuda_runtime.h>
#include <cuda_fp16.h>
#include <cstdint>

#define BATCH 4
#define SEQ   2048
#define DMODEL 1024
#define NHEAD 16
#define DHEAD 64
#define NTOK  (BATCH*SEQ)   // 8192
#define MM    (DMODEL*DMODEL)

// ---------------- scratch (__device__ globals: allocation-free) ----------------
__device__ __align__(16) __half g_Ahi[NTOK*DMODEL];
__device__ __align__(16) __half g_Alo[NTOK*DMODEL];
__device__ __align__(16) __half g_WhT[4*MM];          // [N,K] transposed fp16 hi only
__device__ __align__(16) __half g_Qhi[NTOK*DMODEL];
__device__ __align__(16) __half g_Qlo[NTOK*DMODEL];
__device__ __align__(16) __half g_Khi[NTOK*DMODEL];
__device__ __align__(16) __half g_Vhi[NTOK*DMODEL];
__device__ __align__(16) __half g_VThi[NTOK*DMODEL]; // [b,h,dh,seq]
__device__ __align__(16) __half g_Zhi[NTOK*DMODEL];

__device__ __forceinline__ uint32_t smem_u32(const void* p) {
    uint32_t a;
    asm("{ .reg .u64 t; cvta.to.shared.u64 t, %1; cvt.u32.u64 %0, t; }" : "=r"(a) : "l"(p));
    return a;
}

#define MMA_F16(acc, a, b) \
    asm volatile("mma.sync.aligned.m16n8k16.row.col.f32.f16.f16.f32 " \
        "{%0,%1,%2,%3}, {%4,%5,%6,%7}, {%8,%9}, {%0,%1,%2,%3};" \
        : "+f"((acc)[0]), "+f"((acc)[1]), "+f"((acc)[2]), "+f"((acc)[3]) \
        : "r"((a)[0]), "r"((a)[1]), "r"((a)[2]), "r"((a)[3]), "r"((b)[0]), "r"((b)[1]))

#define CPA16(dst, src) \
    asm volatile("cp.async.cg.shared.global [%0], [%1], 16;" :: "r"(dst), "l"(src) : "memory")

// ---------------- conversion kernels (fp32 -> fp16 hi/lo split) ----------------
__device__ __forceinline__ void split2h(float a, float b, __half2& h, __half2& l) {
    __half ha = __float2half_rn(a), hb = __float2half_rn(b);
    __half la = __float2half_rn(a - __half2float(ha));
    __half lb = __float2half_rn(b - __half2float(hb));
    h = __halves2half2(ha, hb);
    l = __halves2half2(la, lb);
}

__global__ void __launch_bounds__(256) conv_resid(const float* __restrict__ src) {
    int i = blockIdx.x * 256 + threadIdx.x;
    float4 v = ((const float4*)src)[i];
    __half2 h01, l01, h23, l23;
    split2h(v.x, v.y, h01, l01);
    split2h(v.z, v.w, h23, l23);
    ((__half2*)g_Ahi)[2*i]   = h01; ((__half2*)g_Ahi)[2*i+1] = h23;
    ((__half2*)g_Alo)[2*i]   = l01; ((__half2*)g_Alo)[2*i+1] = l23;
}

// All 4 weights in one launch: blockIdx.z = widx; widx==3 applies [dh,h,d] row remap.
__global__ void __launch_bounds__(1024) conv_W4(const float* __restrict__ WQ,
                                                const float* __restrict__ WK,
                                                const float* __restrict__ WV,
                                                const float* __restrict__ WO) {
    __shared__ float t[32][33];
    int widx = blockIdx.z;
    const float* src = (widx == 0) ? WQ : (widx == 1) ? WK : (widx == 2) ? WV : WO;
    int tx = threadIdx.x, ty = threadIdx.y;
    int k = blockIdx.y * 32 + ty, n = blockIdx.x * 32 + tx;
    int sk = (widx == 3) ? ((k & 63) * 16 + (k >> 6)) : k;
    t[ty][tx] = src[sk * DMODEL + n];
    __syncthreads();
    int n2 = blockIdx.x * 32 + ty, k2 = blockIdx.y * 32 + tx;
    g_WhT[(size_t)widx * MM + (size_t)n2 * DMODEL + k2] = __float2half_rn(t[tx][ty]);
}

// V [token][h*64+dh] -> VT [b,h,dh,seq]
__global__ void __launch_bounds__(256) trans_V() {
    __shared__ __half t[32][33];
    int tx = threadIdx.x, ty = threadIdx.y;   // 32 x 8
    int bh = blockIdx.y >> 1, dt = blockIdx.y & 1;
    int b = bh >> 4, h = bh & 15;
    #pragma unroll
    for (int j = 0; j < 4; j++) {
        int s = blockIdx.x * 32 + ty + j * 8;
        t[ty + j*8][tx] = g_Vhi[(size_t)(b*SEQ + s) * DMODEL + h*64 + dt*32 + tx];
    }
    __syncthreads();
    #pragma unroll
    for (int j = 0; j < 4; j++) {
        int dh = dt*32 + ty + j*8;
        g_VThi[(size_t)(bh*64 + dh) * SEQ + blockIdx.x*32 + tx] = t[tx][ty + j*8];
    }
}

// ---------------- split-fp16 HMMA GEMM: C = alpha*((Ahi[+Alo])@Bh^T) ----------------
#define KC    32
#define NCH   (DMODEL / KC)
#define NSTG  3
#define APAD  40
#define ROWB  (APAD * 2)
#define TILE_B (128 * ROWB)
// stage size depends on pass count: (NPASS+1) tiles
#define GEMM_SMEM_2P (NSTG * 3 * TILE_B)   // 92160
#define GEMM_SMEM_1P (NSTG * 2 * TILE_B)   // 61440

__device__ __forceinline__ void load_tile(uint32_t sdst, const __half* __restrict__ g,
                                          int row0, int k0, int tid) {
    const char* gb = (const char*)(g + (size_t)row0 * DMODEL + k0);
    #pragma unroll
    for (int i = 0; i < 2; i++) {
        int id = i * 256 + tid;
        int r = id >> 2, c = id & 3;
        uint32_t sd = sdst + (uint32_t)(r * ROWB + c * 16);
        const char* gp = gb + (size_t)r * (DMODEL * 2) + c * 16;
        CPA16(sd, gp);
    }
}

// OUTMODE 0: fp32 C + bias; 1: hi+lo fp16 outputs; 2: hi-only fp16 output
// NPASS 2: (Ahi+Alo)@B ; NPASS 1: Ahi@B
template<int OUTMODE, int NPASS>
__device__ __forceinline__ void gemm_hmma(const __half* __restrict__ Ahi,
                                          const __half* __restrict__ Alo,
                                          const __half* __restrict__ Bh,
                                          float* __restrict__ C,
                                          const float* __restrict__ bias,
                                          __half* __restrict__ Chi,
                                          __half* __restrict__ Clo,
                                          float alpha)
{
    const int STG_B = (NPASS + 1) * TILE_B;
    extern __shared__ char sm[];
    uint32_t sbase = smem_u32(sm);

    int tid  = threadIdx.x;
    int wid  = tid >> 5, lane = tid & 31;
    int gr   = lane >> 2;
    int lc2  = (lane & 3) * 2;
    int wm   = (wid & 3) * 32;
    int wn   = (wid >> 2) * 64;
    int brow = blockIdx.y * 128;
    int bcol = blockIdx.x * 128;

    float acc[2][8][4];
    #pragma unroll
    for (int i = 0; i < 2; i++)
        #pragma unroll
        for (int j = 0; j < 8; j++)
            #pragma unroll
            for (int q = 0; q < 4; q++) acc[i][j][q] = 0.f;

    #pragma unroll
    for (int s = 0; s < NSTG; s++) {
        uint32_t stg = sbase + s * STG_B;
        int k0 = s * KC;
        load_tile(stg, Ahi, brow, k0, tid);
        if (NPASS == 2) load_tile(stg + TILE_B, Alo, brow, k0, tid);
        load_tile(stg + NPASS*TILE_B, Bh, bcol, k0, tid);
        asm volatile("cp.async.commit_group;" ::: "memory");
    }

    for (int c = 0; c < NCH; c++) {
        int rem = NCH - 1 - c;
        if (rem >= 2)      asm volatile("cp.async.wait_group 2;" ::: "memory");
        else if (rem == 1) asm volatile("cp.async.wait_group 1;" ::: "memory");
        else               asm volatile("cp.async.wait_group 0;" ::: "memory");
        __syncthreads();

        const char* stg = sm + (size_t)(c % NSTG) * STG_B;
        const char* pAh = stg;
        const char* pAl = stg + TILE_B;
        const char* pBh = stg + NPASS*TILE_B;

        #pragma unroll
        for (int ks = 0; ks < 2; ks++) {
            int k0b = ks * 32;
            uint32_t ah[2][4], al[2][4], bh[8][2];
            #pragma unroll
            for (int mt = 0; mt < 2; mt++) {
                const char* p = pAh + (wm + mt*16 + gr) * ROWB + k0b + lc2*2;
                ah[mt][0] = *(const uint32_t*)p;
                ah[mt][1] = *(const uint32_t*)(p + 8*ROWB);
                ah[mt][2] = *(const uint32_t*)(p + 16);
                ah[mt][3] = *(const uint32_t*)(p + 8*ROWB + 16);
                if (NPASS == 2) {
                    const char* q = pAl + (wm + mt*16 + gr) * ROWB + k0b + lc2*2;
                    al[mt][0] = *(const uint32_t*)q;
                    al[mt][1] = *(const uint32_t*)(q + 8*ROWB);
                    al[mt][2] = *(const uint32_t*)(q + 16);
                    al[mt][3] = *(const uint32_t*)(q + 8*ROWB + 16);
                }
            }
            #pragma unroll
            for (int nt = 0; nt < 8; nt++) {
                const char* p = pBh + (wn + nt*8 + gr) * ROWB + k0b + lc2*2;
                bh[nt][0] = *(const uint32_t*)p;
                bh[nt][1] = *(const uint32_t*)(p + 16);
            }
            #pragma unroll
            for (int mt = 0; mt < 2; mt++)
                #pragma unroll
                for (int nt = 0; nt < 8; nt++) {
                    MMA_F16(acc[mt][nt], ah[mt], bh[nt]);
                    if (NPASS == 2) MMA_F16(acc[mt][nt], al[mt], bh[nt]);
                }
        }
        __syncthreads();

        if (c + NSTG < NCH) {
            uint32_t stg2 = sbase + ((c + NSTG) % NSTG) * STG_B;
            int k0 = (c + NSTG) * KC;
            load_tile(stg2, Ahi, brow, k0, tid);
            if (NPASS == 2) load_tile(stg2 + TILE_B, Alo, brow, k0, tid);
            load_tile(stg2 + NPASS*TILE_B, Bh, bcol, k0, tid);
            asm volatile("cp.async.commit_group;" ::: "memory");
        }
    }

    #pragma unroll
    for (int mt = 0; mt < 2; mt++) {
        int r0 = brow + wm + mt*16 + gr;
        #pragma unroll
        for (int nt = 0; nt < 8; nt++) {
            int c0 = bcol + wn + nt*8 + lc2;
            if (OUTMODE == 0) {
                float bx = bias[c0], by = bias[c0 + 1];
                float2 v0, v1;
                v0.x = acc[mt][nt][0] * alpha + bx;
                v0.y = acc[mt][nt][1] * alpha + by;
                v1.x = acc[mt][nt][2] * alpha + bx;
                v1.y = acc[mt][nt][3] * alpha + by;
                *(float2*)&C[(size_t)r0 * DMODEL + c0]       = v0;
                *(float2*)&C[(size_t)(r0 + 8) * DMODEL + c0] = v1;
            } else if (OUTMODE == 1) {
                __half2 h, l;
                split2h(acc[mt][nt][0] * alpha, acc[mt][nt][1] * alpha, h, l);
                *(__half2*)&Chi[(size_t)r0 * DMODEL + c0] = h;
                *(__half2*)&Clo[(size_t)r0 * DMODEL + c0] = l;
                split2h(acc[mt][nt][2] * alpha, acc[mt][nt][3] * alpha, h, l);
                *(__half2*)&Chi[(size_t)(r0+8) * DMODEL + c0] = h;
                *(__half2*)&Clo[(size_t)(r0+8) * DMODEL + c0] = l;
            } else {
                *(__half2*)&Chi[(size_t)r0 * DMODEL + c0] =
                    __floats2half2_rn(acc[mt][nt][0] * alpha, acc[mt][nt][1] * alpha);
                *(__half2*)&Chi[(size_t)(r0+8) * DMODEL + c0] =
                    __floats2half2_rn(acc[mt][nt][2] * alpha, acc[mt][nt][3] * alpha);
            }
        }
    }
}

__global__ void __launch_bounds__(256, 2) qkv_tc_kernel() {
    int z = blockIdx.z;
    const __half* Bh = g_WhT + (size_t)z * MM;
    if (z == 0)
        gemm_hmma<1, 2>(g_Ahi, g_Alo, Bh, nullptr, nullptr, g_Qhi, g_Qlo, 0.125f);
    else if (z == 1)
        gemm_hmma<2, 2>(g_Ahi, g_Alo, Bh, nullptr, nullptr, g_Khi, nullptr, 1.0f);
    else
        gemm_hmma<2, 2>(g_Ahi, g_Alo, Bh, nullptr, nullptr, g_Vhi, nullptr, 1.0f);
}

__global__ void __launch_bounds__(256, 2) out_tc_kernel(const float* __restrict__ bias,
                                                        float* __restrict__ out) {
    gemm_hmma<0, 1>(g_Zhi, nullptr, g_WhT + 3ull*MM, out, bias, nullptr, nullptr, 1.0f);
}

// ---------------- split-fp16 flash attention (causal); P·V single-pass ----------------
#define AROW 144
#define QREG (128 * AROW)
#define TREG (64 * AROW)
#define STAGE2 (2 * TREG)        // Khi, VThi
#define ATT2_SMEM (2*QREG + 2*STAGE2)   // 73728

__device__ __forceinline__ void load_att_stage(uint32_t dst, int b, int h, int kt, int tid) {
    int s0 = kt * 64;
    const char* gkh = (const char*)g_Khi  + ((size_t)(b*SEQ + s0) * DMODEL + h*64) * 2;
    const char* gvh = (const char*)g_VThi + ((size_t)((b*NHEAD + h) * DHEAD) * SEQ + s0) * 2;
    #pragma unroll
    for (int i = 0; i < 2; i++) {
        int idx = i * 256 + tid;
        int r = idx >> 3, c = idx & 7;
        uint32_t off = (uint32_t)(r * AROW + c * 16);
        CPA16(dst + off,        gkh + (size_t)r * (DMODEL*2) + c*16);
        CPA16(dst + TREG + off, gvh + (size_t)r * (SEQ*2) + c*16);
    }
}

__global__ void __launch_bounds__(256, 1) attn2_kernel() {
    extern __shared__ char sm[];
    uint32_t sq = smem_u32(sm);

    int tid = threadIdx.x, wid = tid >> 5, lane = tid & 31;
    int gr = lane >> 2, lq = (lane & 3) * 2;
    int qt = blockIdx.x, h = blockIdx.y, b = blockIdx.z;
    int q0 = qt * 128, wm = wid * 16;

    {
        const char* gqh = (const char*)g_Qhi + ((size_t)(b*SEQ + q0) * DMODEL + h*64) * 2;
        const char* gql = (const char*)g_Qlo + ((size_t)(b*SEQ + q0) * DMODEL + h*64) * 2;
        #pragma unroll
        for (int i = 0; i < 4; i++) {
            int idx = i * 256 + tid;
            int r = idx >> 3, c = idx & 7;
            uint32_t off = (uint32_t)(r * AROW + c * 16);
            CPA16(sq + off,        gqh + (size_t)r * (DMODEL*2) + c*16);
            CPA16(sq + QREG + off, gql + (size_t)r * (DMODEL*2) + c*16);
        }
    }
    load_att_stage(sq + 2*QREG, b, h, 0, tid);
    asm volatile("cp.async.commit_group;" ::: "memory");

    int nkt = 2*qt + 2;
    float m0 = -1e30f, m1 = -1e30f, l0 = 0.f, l1 = 0.f;
    float O[8][4];
    #pragma unroll
    for (int i = 0; i < 8; i++)
        #pragma unroll
        for (int j = 0; j < 4; j++) O[i][j] = 0.f;

    const char* qhi = sm;
    int r0g = q0 + wm + gr, r1g = r0g + 8;

    for (int kt = 0; kt < nkt; kt++) {
        int buf = kt & 1;
        if (kt + 1 < nkt) {
            load_att_stage(sq + 2*QREG + (buf^1)*STAGE2, b, h, kt + 1, tid);
            asm volatile("cp.async.commit_group;" ::: "memory");
            asm volatile("cp.async.wait_group 1;" ::: "memory");
        } else {
            asm volatile("cp.async.wait_group 0;" ::: "memory");
        }
        __syncthreads();

        int s0 = kt * 64;
        if (s0 <= q0 + wm + 15) {
            const char* st  = sm + 2*QREG + buf*STAGE2;
            const char* kh  = st;
            const char* vth = st + TREG;

            float S[8][4];
            #pragma unroll
            for (int i = 0; i < 8; i++)
                #pragma unroll
                for (int j = 0; j < 4; j++) S[i][j] = 0.f;

            #pragma unroll
            for (int ks = 0; ks < 4; ks++) {
                const char* pa = qhi + (wm + gr) * AROW + ks*32 + lq*2;
                uint32_t ah[4], al[4];
                ah[0] = *(const uint32_t*)pa;
                ah[1] = *(const uint32_t*)(pa + 8*AROW);
                ah[2] = *(const uint32_t*)(pa + 16);
                ah[3] = *(const uint32_t*)(pa + 8*AROW + 16);
                al[0] = *(const uint32_t*)(pa + QREG);
                al[1] = *(const uint32_t*)(pa + QREG + 8*AROW);
                al[2] = *(const uint32_t*)(pa + QREG + 16);
                al[3] = *(const uint32_t*)(pa + QREG + 8*AROW + 16);
                #pragma unroll
                for (int nt = 0; nt < 8; nt++) {
                    const char* pb = kh + (nt*8 + gr) * AROW + ks*32 + lq*2;
                    uint32_t bh[2];
                    bh[0] = *(const uint32_t*)pb;
                    bh[1] = *(const uint32_t*)(pb + 16);
                    MMA_F16(S[nt], ah, bh);
                    MMA_F16(S[nt], al, bh);
                }
            }

            if (s0 + 63 > q0 + wm) {
                #pragma unroll
                for (int nt = 0; nt < 8; nt++) {
                    int c0 = s0 + nt*8 + lq;
                    if (c0     > r0g) S[nt][0] = -1e30f;
                    if (c0 + 1 > r0g) S[nt][1] = -1e30f;
                    if (c0     > r1g) S[nt][2] = -1e30f;
                    if (c0 + 1 > r1g) S[nt][3] = -1e30f;
                }
            }

            float mx0 = -1e30f, mx1 = -1e30f;
            #pragma unroll
            for (int nt = 0; nt < 8; nt++) {
                mx0 = fmaxf(mx0, fmaxf(S[nt][0], S[nt][1]));
                mx1 = fmaxf(mx1, fmaxf(S[nt][2], S[nt][3]));
            }
            mx0 = fmaxf(mx0, __shfl_xor_sync(0xffffffffu, mx0, 1));
            mx0 = fmaxf(mx0, __shfl_xor_sync(0xffffffffu, mx0, 2));
            mx1 = fmaxf(mx1, __shfl_xor_sync(0xffffffffu, mx1, 1));
            mx1 = fmaxf(mx1, __shfl_xor_sync(0xffffffffu, mx1, 2));
            float mn0 = fmaxf(m0, mx0), mn1 = fmaxf(m1, mx1);
            float a0 = __expf(m0 - mn0), a1 = __expf(m1 - mn1);

            float sum0 = 0.f, sum1 = 0.f;
            uint32_t pH[8][2];
            #pragma unroll
            for (int nt = 0; nt < 8; nt++) {
                float p0 = __expf(S[nt][0] - mn0);
                float p1 = __expf(S[nt][1] - mn0);
                float p2 = __expf(S[nt][2] - mn1);
                float p3 = __expf(S[nt][3] - mn1);
                sum0 += p0 + p1; sum1 += p2 + p3;
                __half2 h01 = __floats2half2_rn(p0, p1);
                __half2 h23 = __floats2half2_rn(p2, p3);
                pH[nt][0] = *(uint32_t*)&h01;
                pH[nt][1] = *(uint32_t*)&h23;
            }
            sum0 += __shfl_xor_sync(0xffffffffu, sum0, 1);
            sum0 += __shfl_xor_sync(0xffffffffu, sum0, 2);
            sum1 += __shfl_xor_sync(0xffffffffu, sum1, 1);
            sum1 += __shfl_xor_sync(0xffffffffu, sum1, 2);

            m0 = mn0; m1 = mn1;
            l0 = l0 * a0 + sum0;
            l1 = l1 * a1 + sum1;
            #pragma unroll
            for (int nt = 0; nt < 8; nt++) {
                O[nt][0] *= a0; O[nt][1] *= a0;
                O[nt][2] *= a1; O[nt][3] *= a1;
            }

            #pragma unroll
            for (int ks = 0; ks < 4; ks++) {
                uint32_t aH[4] = { pH[2*ks][0], pH[2*ks][1], pH[2*ks+1][0], pH[2*ks+1][1] };
                #pragma unroll
                for (int nt = 0; nt < 8; nt++) {
                    const char* pv = vth + (nt*8 + gr) * AROW + ks*32 + lq*2;
                    uint32_t bvh[2];
                    bvh[0] = *(const uint32_t*)pv;
                    bvh[1] = *(const uint32_t*)(pv + 16);
                    MMA_F16(O[nt], aH, bvh);
                }
            }
        }
        __syncthreads();
    }

    float inv0 = 1.f / l0, inv1 = 1.f / l1;
    size_t t0 = (size_t)(b*SEQ + q0 + wm + gr) * DMODEL + h*64;
    size_t t1 = t0 + 8 * DMODEL;
    #pragma unroll
    for (int nt = 0; nt < 8; nt++) {
        int c0 = nt*8 + lq;
        *(__half2*)&g_Zhi[t0 + c0] = __floats2half2_rn(O[nt][0] * inv0, O[nt][1] * inv0);
        *(__half2*)&g_Zhi[t1 + c0] = __floats2half2_rn(O[nt][2] * inv1, O[nt][3] * inv1);
    }
}

// ---------------------------------------------------------------------------
extern "C" void kernel_launch(void* const* d_in, const int* in_sizes, int n_in,
                              void* d_out, int out_size)
{
    const float* resid = (const float*)d_in[0];
    const float* WQ    = (const float*)d_in[1];
    const float* WK    = (const float*)d_in[2];
    const float* WV    = (const float*)d_in[3];
    const float* Wout  = (const float*)d_in[4];
    const float* bout  = (const float*)d_in[5];
    float* out = (float*)d_out;

    cudaFuncSetAttribute(qkv_tc_kernel, cudaFuncAttributeMaxDynamicSharedMemorySize, GEMM_SMEM_2P);
    cudaFuncSetAttribute(out_tc_kernel, cudaFuncAttributeMaxDynamicSharedMemorySize, GEMM_SMEM_1P);
    cudaFuncSetAttribute(attn2_kernel,  cudaFuncAttributeMaxDynamicSharedMemorySize, ATT2_SMEM);

    conv_resid<<<NTOK*DMODEL/4/256, 256>>>(resid);
    conv_W4<<<dim3(32, 32, 4), dim3(32, 32)>>>(WQ, WK, WV, Wout);

    qkv_tc_kernel<<<dim3(DMODEL/128, NTOK/128, 3), 256, GEMM_SMEM_2P>>>();

    trans_V<<<dim3(SEQ/32, 2*BATCH*NHEAD), dim3(32, 8)>>>();

    attn2_kernel<<<dim3(SEQ/128, NHEAD, BATCH), 256, ATT2_SMEM>>>();

    out_tc_kernel<<<dim3(DMODEL/128, NTOK/128, 1), 256, GEMM_SMEM_1P>>>(bout, out);
}

// round 9
// speedup vs baseline: 1.3517x; 1.1952x over previous
#include <cuda_runtime.h>
#include <cuda_fp16.h>
#include <cstdint>

#define BATCH 4
#define SEQ   2048
#define DMODEL 1024
#define NHEAD 16
#define DHEAD 64
#define NTOK  (BATCH*SEQ)   // 8192
#define MM    (DMODEL*DMODEL)

// ---------------- scratch (__device__ globals: allocation-free) ----------------
__device__ __align__(16) __half g_Ahi[NTOK*DMODEL];
__device__ __align__(16) __half g_Alo[NTOK*DMODEL];
__device__ __align__(16) __half g_WhT[4*MM];          // [N,K] transposed fp16 hi only
__device__ __align__(16) __half g_Qhi[NTOK*DMODEL];
__device__ __align__(16) __half g_Khi[NTOK*DMODEL];
__device__ __align__(16) __half g_Vhi[NTOK*DMODEL];
__device__ __align__(16) __half g_VThi[NTOK*DMODEL]; // [b,h,dh,seq]
__device__ __align__(16) __half g_Zhi[NTOK*DMODEL];

__device__ __forceinline__ uint32_t smem_u32(const void* p) {
    uint32_t a;
    asm("{ .reg .u64 t; cvta.to.shared.u64 t, %1; cvt.u32.u64 %0, t; }" : "=r"(a) : "l"(p));
    return a;
}

#define MMA_F16(acc, a, b) \
    asm volatile("mma.sync.aligned.m16n8k16.row.col.f32.f16.f16.f32 " \
        "{%0,%1,%2,%3}, {%4,%5,%6,%7}, {%8,%9}, {%0,%1,%2,%3};" \
        : "+f"((acc)[0]), "+f"((acc)[1]), "+f"((acc)[2]), "+f"((acc)[3]) \
        : "r"((a)[0]), "r"((a)[1]), "r"((a)[2]), "r"((a)[3]), "r"((b)[0]), "r"((b)[1]))

#define CPA16(dst, src) \
    asm volatile("cp.async.cg.shared.global [%0], [%1], 16;" :: "r"(dst), "l"(src) : "memory")

// ---------------- conversion kernels (fp32 -> fp16 hi/lo split) ----------------
__device__ __forceinline__ void split2h(float a, float b, __half2& h, __half2& l) {
    __half ha = __float2half_rn(a), hb = __float2half_rn(b);
    __half la = __float2half_rn(a - __half2float(ha));
    __half lb = __float2half_rn(b - __half2float(hb));
    h = __halves2half2(ha, hb);
    l = __halves2half2(la, lb);
}

__global__ void __launch_bounds__(256) conv_resid(const float* __restrict__ src) {
    int i = blockIdx.x * 256 + threadIdx.x;
    float4 v = ((const float4*)src)[i];
    __half2 h01, l01, h23, l23;
    split2h(v.x, v.y, h01, l01);
    split2h(v.z, v.w, h23, l23);
    ((__half2*)g_Ahi)[2*i]   = h01; ((__half2*)g_Ahi)[2*i+1] = h23;
    ((__half2*)g_Alo)[2*i]   = l01; ((__half2*)g_Alo)[2*i+1] = l23;
}

// All 4 weights in one launch: blockIdx.z = widx; widx==3 applies [dh,h,d] row remap.
__global__ void __launch_bounds__(1024) conv_W4(const float* __restrict__ WQ,
                                                const float* __restrict__ WK,
                                                const float* __restrict__ WV,
                                                const float* __restrict__ WO) {
    __shared__ float t[32][33];
    int widx = blockIdx.z;
    const float* src = (widx == 0) ? WQ : (widx == 1) ? WK : (widx == 2) ? WV : WO;
    int tx = threadIdx.x, ty = threadIdx.y;
    int k = blockIdx.y * 32 + ty, n = blockIdx.x * 32 + tx;
    int sk = (widx == 3) ? ((k & 63) * 16 + (k >> 6)) : k;
    t[ty][tx] = src[sk * DMODEL + n];
    __syncthreads();
    int n2 = blockIdx.x * 32 + ty, k2 = blockIdx.y * 32 + tx;
    g_WhT[(size_t)widx * MM + (size_t)n2 * DMODEL + k2] = __float2half_rn(t[tx][ty]);
}

// V [token][h*64+dh] -> VT [b,h,dh,seq]
__global__ void __launch_bounds__(256) trans_V() {
    __shared__ __half t[32][33];
    int tx = threadIdx.x, ty = threadIdx.y;   // 32 x 8
    int bh = blockIdx.y >> 1, dt = blockIdx.y & 1;
    int b = bh >> 4, h = bh & 15;
    #pragma unroll
    for (int j = 0; j < 4; j++) {
        int s = blockIdx.x * 32 + ty + j * 8;
        t[ty + j*8][tx] = g_Vhi[(size_t)(b*SEQ + s) * DMODEL + h*64 + dt*32 + tx];
    }
    __syncthreads();
    #pragma unroll
    for (int j = 0; j < 4; j++) {
        int dh = dt*32 + ty + j*8;
        g_VThi[(size_t)(bh*64 + dh) * SEQ + blockIdx.x*32 + tx] = t[tx][ty + j*8];
    }
}

// ---------------- split-fp16 HMMA GEMM: C = alpha*((Ahi[+Alo])@Bh^T) ----------------
#define KC    32
#define NCH   (DMODEL / KC)
#define NSTG  3
#define APAD  40
#define ROWB  (APAD * 2)
#define TILE_B (128 * ROWB)
#define GEMM_SMEM_2P (NSTG * 3 * TILE_B)   // 92160
#define GEMM_SMEM_1P (NSTG * 2 * TILE_B)   // 61440

__device__ __forceinline__ void load_tile(uint32_t sdst, const __half* __restrict__ g,
                                          int row0, int k0, int tid) {
    const char* gb = (const char*)(g + (size_t)row0 * DMODEL + k0);
    #pragma unroll
    for (int i = 0; i < 2; i++) {
        int id = i * 256 + tid;
        int r = id >> 2, c = id & 3;
        uint32_t sd = sdst + (uint32_t)(r * ROWB + c * 16);
        const char* gp = gb + (size_t)r * (DMODEL * 2) + c * 16;
        CPA16(sd, gp);
    }
}

// OUTMODE 0: fp32 C + bias; 2: hi-only fp16 output
// NPASS 2: (Ahi+Alo)@B ; NPASS 1: Ahi@B
template<int OUTMODE, int NPASS>
__device__ __forceinline__ void gemm_hmma(const __half* __restrict__ Ahi,
                                          const __half* __restrict__ Alo,
                                          const __half* __restrict__ Bh,
                                          float* __restrict__ C,
                                          const float* __restrict__ bias,
                                          __half* __restrict__ Chi,
                                          float alpha)
{
    const int STG_B = (NPASS + 1) * TILE_B;
    extern __shared__ char sm[];
    uint32_t sbase = smem_u32(sm);

    int tid  = threadIdx.x;
    int wid  = tid >> 5, lane = tid & 31;
    int gr   = lane >> 2;
    int lc2  = (lane & 3) * 2;
    int wm   = (wid & 3) * 32;
    int wn   = (wid >> 2) * 64;
    int brow = blockIdx.y * 128;
    int bcol = blockIdx.x * 128;

    float acc[2][8][4];
    #pragma unroll
    for (int i = 0; i < 2; i++)
        #pragma unroll
        for (int j = 0; j < 8; j++)
            #pragma unroll
            for (int q = 0; q < 4; q++) acc[i][j][q] = 0.f;

    #pragma unroll
    for (int s = 0; s < NSTG; s++) {
        uint32_t stg = sbase + s * STG_B;
        int k0 = s * KC;
        load_tile(stg, Ahi, brow, k0, tid);
        if (NPASS == 2) load_tile(stg + TILE_B, Alo, brow, k0, tid);
        load_tile(stg + NPASS*TILE_B, Bh, bcol, k0, tid);
        asm volatile("cp.async.commit_group;" ::: "memory");
    }

    for (int c = 0; c < NCH; c++) {
        int rem = NCH - 1 - c;
        if (rem >= 2)      asm volatile("cp.async.wait_group 2;" ::: "memory");
        else if (rem == 1) asm volatile("cp.async.wait_group 1;" ::: "memory");
        else               asm volatile("cp.async.wait_group 0;" ::: "memory");
        __syncthreads();

        const char* stg = sm + (size_t)(c % NSTG) * STG_B;
        const char* pAh = stg;
        const char* pAl = stg + TILE_B;
        const char* pBh = stg + NPASS*TILE_B;

        #pragma unroll
        for (int ks = 0; ks < 2; ks++) {
            int k0b = ks * 32;
            uint32_t ah[2][4], al[2][4], bh[8][2];
            #pragma unroll
            for (int mt = 0; mt < 2; mt++) {
                const char* p = pAh + (wm + mt*16 + gr) * ROWB + k0b + lc2*2;
                ah[mt][0] = *(const uint32_t*)p;
                ah[mt][1] = *(const uint32_t*)(p + 8*ROWB);
                ah[mt][2] = *(const uint32_t*)(p + 16);
                ah[mt][3] = *(const uint32_t*)(p + 8*ROWB + 16);
                if (NPASS == 2) {
                    const char* q = pAl + (wm + mt*16 + gr) * ROWB + k0b + lc2*2;
                    al[mt][0] = *(const uint32_t*)q;
                    al[mt][1] = *(const uint32_t*)(q + 8*ROWB);
                    al[mt][2] = *(const uint32_t*)(q + 16);
                    al[mt][3] = *(const uint32_t*)(q + 8*ROWB + 16);
                }
            }
            #pragma unroll
            for (int nt = 0; nt < 8; nt++) {
                const char* p = pBh + (wn + nt*8 + gr) * ROWB + k0b + lc2*2;
                bh[nt][0] = *(const uint32_t*)p;
                bh[nt][1] = *(const uint32_t*)(p + 16);
            }
            #pragma unroll
            for (int mt = 0; mt < 2; mt++)
                #pragma unroll
                for (int nt = 0; nt < 8; nt++) {
                    MMA_F16(acc[mt][nt], ah[mt], bh[nt]);
                    if (NPASS == 2) MMA_F16(acc[mt][nt], al[mt], bh[nt]);
                }
        }
        __syncthreads();

        if (c + NSTG < NCH) {
            uint32_t stg2 = sbase + ((c + NSTG) % NSTG) * STG_B;
            int k0 = (c + NSTG) * KC;
            load_tile(stg2, Ahi, brow, k0, tid);
            if (NPASS == 2) load_tile(stg2 + TILE_B, Alo, brow, k0, tid);
            load_tile(stg2 + NPASS*TILE_B, Bh, bcol, k0, tid);
            asm volatile("cp.async.commit_group;" ::: "memory");
        }
    }

    #pragma unroll
    for (int mt = 0; mt < 2; mt++) {
        int r0 = brow + wm + mt*16 + gr;
        #pragma unroll
        for (int nt = 0; nt < 8; nt++) {
            int c0 = bcol + wn + nt*8 + lc2;
            if (OUTMODE == 0) {
                float bx = bias[c0], by = bias[c0 + 1];
                float2 v0, v1;
                v0.x = acc[mt][nt][0] * alpha + bx;
                v0.y = acc[mt][nt][1] * alpha + by;
                v1.x = acc[mt][nt][2] * alpha + bx;
                v1.y = acc[mt][nt][3] * alpha + by;
                *(float2*)&C[(size_t)r0 * DMODEL + c0]       = v0;
                *(float2*)&C[(size_t)(r0 + 8) * DMODEL + c0] = v1;
            } else {
                *(__half2*)&Chi[(size_t)r0 * DMODEL + c0] =
                    __floats2half2_rn(acc[mt][nt][0] * alpha, acc[mt][nt][1] * alpha);
                *(__half2*)&Chi[(size_t)(r0+8) * DMODEL + c0] =
                    __floats2half2_rn(acc[mt][nt][2] * alpha, acc[mt][nt][3] * alpha);
            }
        }
    }
}

__global__ void __launch_bounds__(256, 2) qkv_tc_kernel() {
    int z = blockIdx.z;
    const __half* Bh = g_WhT + (size_t)z * MM;
    if (z == 0)       // Q: 2-pass (A error feeds scores through 1024-deep dot)
        gemm_hmma<2, 2>(g_Ahi, g_Alo, Bh, nullptr, nullptr, g_Qhi, 0.125f);
    else if (z == 1)  // K: 2-pass (same sensitivity as Q)
        gemm_hmma<2, 2>(g_Ahi, g_Alo, Bh, nullptr, nullptr, g_Khi, 1.0f);
    else              // V: 1-pass (error damped by softmax convex combination)
        gemm_hmma<2, 1>(g_Ahi, nullptr, Bh, nullptr, nullptr, g_Vhi, 1.0f);
}

__global__ void __launch_bounds__(256, 2) out_tc_kernel(const float* __restrict__ bias,
                                                        float* __restrict__ out) {
    gemm_hmma<0, 1>(g_Zhi, nullptr, g_WhT + 3ull*MM, out, bias, nullptr, 1.0f);
}

// ---------------- fp16 flash attention (causal); S and P·V single-pass ----------------
#define AROW 144
#define QREG (128 * AROW)
#define TREG (64 * AROW)
#define STAGE2 (2 * TREG)        // Khi, VThi
#define ATT2_SMEM (QREG + 2*STAGE2)   // 55296

__device__ __forceinline__ void load_att_stage(uint32_t dst, int b, int h, int kt, int tid) {
    int s0 = kt * 64;
    const char* gkh = (const char*)g_Khi  + ((size_t)(b*SEQ + s0) * DMODEL + h*64) * 2;
    const char* gvh = (const char*)g_VThi + ((size_t)((b*NHEAD + h) * DHEAD) * SEQ + s0) * 2;
    #pragma unroll
    for (int i = 0; i < 2; i++) {
        int idx = i * 256 + tid;
        int r = idx >> 3, c = idx & 7;
        uint32_t off = (uint32_t)(r * AROW + c * 16);
        CPA16(dst + off,        gkh + (size_t)r * (DMODEL*2) + c*16);
        CPA16(dst + TREG + off, gvh + (size_t)r * (SEQ*2) + c*16);
    }
}

__global__ void __launch_bounds__(256, 2) attn2_kernel() {
    extern __shared__ char sm[];
    uint32_t sq = smem_u32(sm);

    int tid = threadIdx.x, wid = tid >> 5, lane = tid & 31;
    int gr = lane >> 2, lq = (lane & 3) * 2;
    int qt = blockIdx.x, h = blockIdx.y, b = blockIdx.z;
    int q0 = qt * 128, wm = wid * 16;

    {
        const char* gqh = (const char*)g_Qhi + ((size_t)(b*SEQ + q0) * DMODEL + h*64) * 2;
        #pragma unroll
        for (int i = 0; i < 4; i++) {
            int idx = i * 256 + tid;
            int r = idx >> 3, c = idx & 7;
            uint32_t off = (uint32_t)(r * AROW + c * 16);
            CPA16(sq + off, gqh + (size_t)r * (DMODEL*2) + c*16);
        }
    }
    load_att_stage(sq + QREG, b, h, 0, tid);
    asm volatile("cp.async.commit_group;" ::: "memory");

    int nkt = 2*qt + 2;
    float m0 = -1e30f, m1 = -1e30f, l0 = 0.f, l1 = 0.f;
    float O[8][4];
    #pragma unroll
    for (int i = 0; i < 8; i++)
        #pragma unroll
        for (int j = 0; j < 4; j++) O[i][j] = 0.f;

    const char* qhi = sm;
    int r0g = q0 + wm + gr, r1g = r0g + 8;

    for (int kt = 0; kt < nkt; kt++) {
        int buf = kt & 1;
        if (kt + 1 < nkt) {
            load_att_stage(sq + QREG + (buf^1)*STAGE2, b, h, kt + 1, tid);
            asm volatile("cp.async.commit_group;" ::: "memory");
            asm volatile("cp.async.wait_group 1;" ::: "memory");
        } else {
            asm volatile("cp.async.wait_group 0;" ::: "memory");
        }
        __syncthreads();

        int s0 = kt * 64;
        if (s0 <= q0 + wm + 15) {
            const char* st  = sm + QREG + buf*STAGE2;
            const char* kh  = st;
            const char* vth = st + TREG;

            float S[8][4];
            #pragma unroll
            for (int i = 0; i < 8; i++)
                #pragma unroll
                for (int j = 0; j < 4; j++) S[i][j] = 0.f;

            #pragma unroll
            for (int ks = 0; ks < 4; ks++) {
                const char* pa = qhi + (wm + gr) * AROW + ks*32 + lq*2;
                uint32_t ah[4];
                ah[0] = *(const uint32_t*)pa;
                ah[1] = *(const uint32_t*)(pa + 8*AROW);
                ah[2] = *(const uint32_t*)(pa + 16);
                ah[3] = *(const uint32_t*)(pa + 8*AROW + 16);
                #pragma unroll
                for (int nt = 0; nt < 8; nt++) {
                    const char* pb = kh + (nt*8 + gr) * AROW + ks*32 + lq*2;
                    uint32_t bh[2];
                    bh[0] = *(const uint32_t*)pb;
                    bh[1] = *(const uint32_t*)(pb + 16);
                    MMA_F16(S[nt], ah, bh);
                }
            }

            if (s0 + 63 > q0 + wm) {
                #pragma unroll
                for (int nt = 0; nt < 8; nt++) {
                    int c0 = s0 + nt*8 + lq;
                    if (c0     > r0g) S[nt][0] = -1e30f;
                    if (c0 + 1 > r0g) S[nt][1] = -1e30f;
                    if (c0     > r1g) S[nt][2] = -1e30f;
                    if (c0 + 1 > r1g) S[nt][3] = -1e30f;
                }
            }

            float mx0 = -1e30f, mx1 = -1e30f;
            #pragma unroll
            for (int nt = 0; nt < 8; nt++) {
                mx0 = fmaxf(mx0, fmaxf(S[nt][0], S[nt][1]));
                mx1 = fmaxf(mx1, fmaxf(S[nt][2], S[nt][3]));
            }
            mx0 = fmaxf(mx0, __shfl_xor_sync(0xffffffffu, mx0, 1));
            mx0 = fmaxf(mx0, __shfl_xor_sync(0xffffffffu, mx0, 2));
            mx1 = fmaxf(mx1, __shfl_xor_sync(0xffffffffu, mx1, 1));
            mx1 = fmaxf(mx1, __shfl_xor_sync(0xffffffffu, mx1, 2));
            float mn0 = fmaxf(m0, mx0), mn1 = fmaxf(m1, mx1);
            float a0 = __expf(m0 - mn0), a1 = __expf(m1 - mn1);

            float sum0 = 0.f, sum1 = 0.f;
            uint32_t pH[8][2];
            #pragma unroll
            for (int nt = 0; nt < 8; nt++) {
                float p0 = __expf(S[nt][0] - mn0);
                float p1 = __expf(S[nt][1] - mn0);
                float p2 = __expf(S[nt][2] - mn1);
                float p3 = __expf(S[nt][3] - mn1);
                sum0 += p0 + p1; sum1 += p2 + p3;
                __half2 h01 = __floats2half2_rn(p0, p1);
                __half2 h23 = __floats2half2_rn(p2, p3);
                pH[nt][0] = *(uint32_t*)&h01;
                pH[nt][1] = *(uint32_t*)&h23;
            }
            sum0 += __shfl_xor_sync(0xffffffffu, sum0, 1);
            sum0 += __shfl_xor_sync(0xffffffffu, sum0, 2);
            sum1 += __shfl_xor_sync(0xffffffffu, sum1, 1);
            sum1 += __shfl_xor_sync(0xffffffffu, sum1, 2);

            m0 = mn0; m1 = mn1;
            l0 = l0 * a0 + sum0;
            l1 = l1 * a1 + sum1;
            #pragma unroll
            for (int nt = 0; nt < 8; nt++) {
                O[nt][0] *= a0; O[nt][1] *= a0;
                O[nt][2] *= a1; O[nt][3] *= a1;
            }

            #pragma unroll
            for (int ks = 0; ks < 4; ks++) {
                uint32_t aH[4] = { pH[2*ks][0], pH[2*ks][1], pH[2*ks+1][0], pH[2*ks+1][1] };
                #pragma unroll
                for (int nt = 0; nt < 8; nt++) {
                    const char* pv = vth + (nt*8 + gr) * AROW + ks*32 + lq*2;
                    uint32_t bvh[2];
                    bvh[0] = *(const uint32_t*)pv;
                    bvh[1] = *(const uint32_t*)(pv + 16);
                    MMA_F16(O[nt], aH, bvh);
                }
            }
        }
        __syncthreads();
    }

    float inv0 = 1.f / l0, inv1 = 1.f / l1;
    size_t t0 = (size_t)(b*SEQ + q0 + wm + gr) * DMODEL + h*64;
    size_t t1 = t0 + 8 * DMODEL;
    #pragma unroll
    for (int nt = 0; nt < 8; nt++) {
        int c0 = nt*8 + lq;
        *(__half2*)&g_Zhi[t0 + c0] = __floats2half2_rn(O[nt][0] * inv0, O[nt][1] * inv0);
        *(__half2*)&g_Zhi[t1 + c0] = __floats2half2_rn(O[nt][2] * inv1, O[nt][3] * inv1);
    }
}

// ---------------------------------------------------------------------------
extern "C" void kernel_launch(void* const* d_in, const int* in_sizes, int n_in,
                              void* d_out, int out_size)
{
    const float* resid = (const float*)d_in[0];
    const float* WQ    = (const float*)d_in[1];
    const float* WK    = (const float*)d_in[2];
    const float* WV    = (const float*)d_in[3];
    const float* Wout  = (const float*)d_in[4];
    const float* bout  = (const float*)d_in[5];
    float* out = (float*)d_out;

    cudaFuncSetAttribute(qkv_tc_kernel, cudaFuncAttributeMaxDynamicSharedMemorySize, GEMM_SMEM_2P);
    cudaFuncSetAttribute(out_tc_kernel, cudaFuncAttributeMaxDynamicSharedMemorySize, GEMM_SMEM_1P);
    cudaFuncSetAttribute(attn2_kernel,  cudaFuncAttributeMaxDynamicSharedMemorySize, ATT2_SMEM);

    conv_resid<<<NTOK*DMODEL/4/256, 256>>>(resid);
    conv_W4<<<dim3(32, 32, 4), dim3(32, 32)>>>(WQ, WK, WV, Wout);

    qkv_tc_kernel<<<dim3(DMODEL/128, NTOK/128, 3), 256, GEMM_SMEM_2P>>>();

    trans_V<<<dim3(SEQ/32, 2*BATCH*NHEAD), dim3(32, 8)>>>();

    attn2_kernel<<<dim3(SEQ/128, NHEAD, BATCH), 256, ATT2_SMEM>>>();

    out_tc_kernel<<<dim3(DMODEL/128, NTOK/128, 1), 256, GEMM_SMEM_1P>>>(bout, out);
}